// round 13
// baseline (speedup 1.0000x reference)
#include <cuda_runtime.h>
#include <math.h>

// ---- problem constants ----
#define Bb 64
#define Nn 256
#define Tt 96
#define Pp 8
#define Ss 4
#define Dd 128
#define Hh 8
#define Kk 16
#define PLl 24
#define Ll 23

// ---- scratch ----
__device__ float g_maskf[Bb*Nn];
__device__ float g_wf[9*256];          // rows 0..7: (Wp@W1)[p][j]; row 8: bp@W1
__device__ __align__(16) float g_hmean[Bb*Nn*Dd];
__device__ int   g_obsidx[Bb*Nn];
__device__ int   g_nobs[Bb];
__device__ __align__(16) float g_q[Bb*Nn*Dd];
__device__ __align__(16) float g_k[Bb*Nn*Dd];
__device__ __align__(16) float g_v[Bb*Nn*Dd];
__device__ float g_attnsum[Bb*Dd];
__device__ float g_toksum[Bb*Dd];
__device__ float g_afill[Bb*Dd];

typedef unsigned long long u64;

#define FMA2(d,a,b,c) asm("fma.rn.f32x2 %0, %1, %2, %3;" : "=l"(d) : "l"(a), "l"(b), "l"(c))
#define MUL2(d,a,b)   asm("mul.rn.f32x2 %0, %1, %2;" : "=l"(d) : "l"(a), "l"(b))
#define ADD2(d,a,b)   asm("add.rn.f32x2 %0, %1, %2;" : "=l"(d) : "l"(a), "l"(b))
#define PACKF2(o,f)   asm("mov.b64 %0, {%1, %1};" : "=l"(o) : "r"(__float_as_uint(f)))
#define PACK2(o,a,b)  asm("mov.b64 %0, {%1, %2};" : "=l"(o) : "r"(__float_as_uint(a)), "r"(__float_as_uint(b)))
#define UNPACK2(a,b,i) asm("mov.b64 {%0, %1}, %2;" : "=r"(a), "=r"(b) : "l"(i))

__device__ __forceinline__ float f2lo(u64 v){ return __uint_as_float((unsigned)(v & 0xffffffffull)); }
__device__ __forceinline__ float f2hi(u64 v){ return __uint_as_float((unsigned)(v >> 32)); }

__device__ __forceinline__ float tanh_fast(float z){
    float t;
    asm("tanh.approx.f32 %0, %1;" : "=f"(t) : "f"(z));
    return t;
}

// ---- fused: blocks 0..63 = mask decode + compaction (per-block dtype sniff);
//             block 64 = fold Wp/bp into W1 ----
__global__ __launch_bounds__(256) void kmaskfold(const unsigned char* __restrict__ mp,
                                                 const float* __restrict__ Wp,
                                                 const float* __restrict__ bp,
                                                 const float* __restrict__ W1){
    int tid = threadIdx.x;
    if (blockIdx.x == Bb){
        __shared__ float sWp[Pp*Dd];
        __shared__ float sbp[Dd];
        for (int i = tid; i < Pp*Dd; i += 256) sWp[i] = Wp[i];
        if (tid < Dd) sbp[tid] = bp[tid];
        __syncthreads();
        int j = tid;
        float acc[9];
        #pragma unroll
        for (int p = 0; p < 9; p++) acc[p] = 0.f;
        for (int d = 0; d < Dd; d++){
            float w1 = W1[d*256 + j];
            #pragma unroll
            for (int p = 0; p < 8; p++) acc[p] += sWp[p*Dd + d]*w1;
            acc[8] += sbp[d]*w1;
        }
        #pragma unroll
        for (int p = 0; p < 9; p++) g_wf[p*256 + j] = acc[p];
        return;
    }
    __shared__ int sawF, sawB;
    __shared__ int wtot[8];
    __shared__ int wbase[9];
    if (tid == 0){ sawF = 0; sawB = 0; }
    __syncthreads();
    for (int i = tid; i < Bb*Nn; i += 256){
        unsigned char c = mp[i];
        if (c == 0x3f || c == 0x80) sawF = 1;
        else if (c != 0 && (i & 3) != 0) sawB = 1;
    }
    __syncthreads();
    int mode = sawF ? 0 : (sawB ? 2 : 1);
    int b = blockIdx.x;
    int i = b*Nn + tid;
    bool m;
    if (mode == 0)      m = ((const float*)mp)[i] != 0.0f;
    else if (mode == 1) m = ((const int*)mp)[i]   != 0;
    else                m = mp[i] != 0;
    g_maskf[i] = m ? 1.0f : 0.0f;
    unsigned bits = __ballot_sync(0xffffffffu, m);
    int w = tid >> 5, lane = tid & 31;
    int rank = __popc(bits & ((1u << lane) - 1u));
    if (lane == 0) wtot[w] = __popc(bits);
    __syncthreads();
    if (tid == 0){
        int s = 0;
        #pragma unroll
        for (int ww = 0; ww < 8; ww++){ wbase[ww] = s; s += wtot[ww]; }
        wbase[8] = s;
        g_nobs[b] = s;
    }
    __syncthreads();
    int total = wbase[8];
    int obs_before = wbase[w] + rank;
    int pos = m ? obs_before : total + (tid - obs_before);
    g_obsidx[b*Nn + pos] = tid;
    if (tid < Dd) g_toksum[b*Dd + tid] = 0.f;
}

// ---- stage 1: h_mean for 16 tokens per block, fully packed f32x2 ----
__global__ __launch_bounds__(256) void kstage1(
    const float* __restrict__ x,
    const float* __restrict__ Wp,
    const float* __restrict__ bp,
    const float* __restrict__ W2){
    __shared__ __align__(16) u64 sxp[8][96];
    __shared__ float sxs[16][Pp];
    __shared__ __align__(16) u64 sG2[256][10];
    __shared__ u64 sv2[8][Dd];
    int tid = threadIdx.x;
    int bn0 = blockIdx.x*16;

    for (int idx = tid; idx < 8*Tt; idx += 256){
        int tp = idx/Tt, c = idx - tp*Tt;
        float lo = x[(bn0+2*tp  )*Tt + c] * g_maskf[bn0+2*tp];
        float hi = x[(bn0+2*tp+1)*Tt + c] * g_maskf[bn0+2*tp+1];
        u64 pk; PACK2(pk, lo, hi);
        sxp[tp][c] = pk;
    }
    __syncthreads();
    if (tid < 128){
        int t = tid >> 3, p = tid & 7;
        int tp = t >> 1, half = t & 1;
        float s = 0.f;
        #pragma unroll
        for (int l = 0; l < Ll; l++){
            u64 v = sxp[tp][l*Ss + p];
            s += half ? f2hi(v) : f2lo(v);
        }
        sxs[t][p] = s;
    }

    {
        int j = tid;
        u64 wf2[8];
        #pragma unroll
        for (int p = 0; p < 8; p++) PACKF2(wf2[p], g_wf[p*256 + j]);
        u64 ub2; PACKF2(ub2, g_wf[8*256 + j]);
        u64 C1P, C2P, HALFP;
        PACKF2(C1P, 0.035677408136f);
        PACKF2(C2P, 0.797884560803f);
        PACKF2(HALFP, 0.5f);
        #pragma unroll 1
        for (int tp = 0; tp < 8; tp++){
            const ulonglong2* xv = (const ulonglong2*)&sxp[tp][0];
            ulonglong2 A = xv[0], Bv = xv[1];
            u64 Gp = 0ull;
            #pragma unroll
            for (int l = 0; l < Ll; l++){
                ulonglong2 Cv = xv[2*l+2], Dv = xv[2*l+3];
                u64 u = ub2;
                FMA2(u, A.x,  wf2[0], u); FMA2(u, A.y,  wf2[1], u);
                FMA2(u, Bv.x, wf2[2], u); FMA2(u, Bv.y, wf2[3], u);
                FMA2(u, Cv.x, wf2[4], u); FMA2(u, Cv.y, wf2[5], u);
                FMA2(u, Dv.x, wf2[6], u); FMA2(u, Dv.y, wf2[7], u);
                u64 x2p; MUL2(x2p, u, u);
                u64 t1;  FMA2(t1, C1P, x2p, C2P);
                u64 zp;  MUL2(zp, u, t1);
                unsigned zl, zh; UNPACK2(zl, zh, zp);
                float tl = tanh_fast(__uint_as_float(zl));
                float th = tanh_fast(__uint_as_float(zh));
                u64 tpk; PACK2(tpk, tl, th);
                u64 hxp; MUL2(hxp, u, HALFP);
                u64 res; FMA2(res, hxp, tpk, hxp);
                ADD2(Gp, Gp, res);
                A = Cv; Bv = Dv;
            }
            sG2[j][tp] = Gp;
        }
    }
    __syncthreads();

    {
        int d = tid & 127, h2 = tid >> 7;
        u64 acc[8];
        #pragma unroll
        for (int tp = 0; tp < 8; tp++) acc[tp] = 0ull;
        int j0 = h2*128;
        for (int j = j0; j < j0+128; j++){
            float w = W2[j*Dd + d];
            u64 w2; PACKF2(w2, w);
            const ulonglong2* gr = (const ulonglong2*)&sG2[j][0];
            ulonglong2 g01 = gr[0], g23 = gr[1], g45 = gr[2], g67 = gr[3];
            FMA2(acc[0], g01.x, w2, acc[0]); FMA2(acc[1], g01.y, w2, acc[1]);
            FMA2(acc[2], g23.x, w2, acc[2]); FMA2(acc[3], g23.y, w2, acc[3]);
            FMA2(acc[4], g45.x, w2, acc[4]); FMA2(acc[5], g45.y, w2, acc[5]);
            FMA2(acc[6], g67.x, w2, acc[6]); FMA2(acc[7], g67.y, w2, acc[7]);
        }
        if (h2){
            #pragma unroll
            for (int tp = 0; tp < 8; tp++) sv2[tp][d] = acc[tp];
        }
        __syncthreads();
        if (!h2){
            float bpd = 23.0f*bp[d];
            float wpc[8];
            #pragma unroll
            for (int p = 0; p < 8; p++) wpc[p] = Wp[p*Dd + d];
            #pragma unroll
            for (int tp = 0; tp < 8; tp++){
                u64 o = sv2[tp][d];
                float lo = f2lo(acc[tp]) + f2lo(o);
                float hi = f2hi(acc[tp]) + f2hi(o);
                int t0 = 2*tp;
                float hs0 = bpd, hs1 = bpd;
                #pragma unroll
                for (int p = 0; p < 8; p++){
                    hs0 += sxs[t0  ][p]*wpc[p];
                    hs1 += sxs[t0+1][p]*wpc[p];
                }
                g_hmean[(bn0+t0  )*Dd + d] = (hs0 + lo) * (1.0f/23.0f);
                g_hmean[(bn0+t0+1)*Dd + d] = (hs1 + hi) * (1.0f/23.0f);
            }
        }
    }
}

// ---- q/k/v: 16 tokens/block, 192 threads = 3 proj x 64 column-pairs ----
__global__ __launch_bounds__(192, 4) void kqkv(
    const float* __restrict__ Wq,
    const float* __restrict__ Wk,
    const float* __restrict__ Wv,
    const float* __restrict__ ve){
    __shared__ __align__(16) float tokT[Dd][20];
    int tid = threadIdx.x;
    int b = blockIdx.x >> 4;
    int i0 = (blockIdx.x & 15) * 16;
    int n = g_nobs[b];
    for (int idx = tid; idx < 16*Dd; idx += 192){
        int t = idx >> 7, d = idx & 127;
        int i = i0 + t;
        float val = 0.f;
        if (i < n){
            int src = g_obsidx[b*Nn + i];
            val = g_hmean[(b*Nn + src)*Dd + d] + ve[src*Dd + d];
        }
        tokT[d][t] = val;
    }
    __syncthreads();
    if (tid < Dd){
        const float4* r = (const float4*)&tokT[tid][0];
        float4 a = r[0], b4 = r[1], c4 = r[2], d4 = r[3];
        float s = a.x+a.y+a.z+a.w + b4.x+b4.y+b4.z+b4.w
                + c4.x+c4.y+c4.z+c4.w + d4.x+d4.y+d4.z+d4.w;
        atomicAdd(&g_toksum[b*Dd + tid], s);
    }
    int which = tid >> 6;
    int c0 = (tid & 63) * 2;
    const float* W = (which == 0) ? Wq : (which == 1 ? Wk : Wv);
    float* dst = (which == 0) ? g_q : (which == 1 ? g_k : g_v);
    u64 a0[8], a1[8];
    #pragma unroll
    for (int r = 0; r < 8; r++){ a0[r] = 0ull; a1[r] = 0ull; }
    for (int d = 0; d < Dd; d++){
        float2 w = *(const float2*)&W[d*Dd + c0];
        u64 w2a, w2b;
        PACKF2(w2a, w.x);
        PACKF2(w2b, w.y);
        const ulonglong2* row = (const ulonglong2*)&tokT[d][0];
        ulonglong2 p0 = row[0], p1 = row[1], p2 = row[2], p3 = row[3];
        FMA2(a0[0], p0.x, w2a, a0[0]); FMA2(a1[0], p0.x, w2b, a1[0]);
        FMA2(a0[1], p0.y, w2a, a0[1]); FMA2(a1[1], p0.y, w2b, a1[1]);
        FMA2(a0[2], p1.x, w2a, a0[2]); FMA2(a1[2], p1.x, w2b, a1[2]);
        FMA2(a0[3], p1.y, w2a, a0[3]); FMA2(a1[3], p1.y, w2b, a1[3]);
        FMA2(a0[4], p2.x, w2a, a0[4]); FMA2(a1[4], p2.x, w2b, a1[4]);
        FMA2(a0[5], p2.y, w2a, a0[5]); FMA2(a1[5], p2.y, w2b, a1[5]);
        FMA2(a0[6], p3.x, w2a, a0[6]); FMA2(a1[6], p3.x, w2b, a1[6]);
        FMA2(a0[7], p3.y, w2a, a0[7]); FMA2(a1[7], p3.y, w2b, a1[7]);
    }
    #pragma unroll
    for (int r = 0; r < 8; r++){
        float2 e0 = make_float2(f2lo(a0[r]), f2lo(a1[r]));
        float2 e1 = make_float2(f2hi(a0[r]), f2hi(a1[r]));
        *(float2*)&dst[(b*Nn + i0 + 2*r    )*Dd + c0] = e0;
        *(float2*)&dst[(b*Nn + i0 + 2*r + 1)*Dd + c0] = e1;
    }
}

// ---- attention per (b,h): 128 threads, 2 queries/iter, smem-broadcast q,
//      no-max softmax (scores provably small) ----
__global__ __launch_bounds__(128, 5) void kattn(){
    __shared__ __align__(16) float ks[Nn][20];   // K rows, conflict-free float4
    __shared__ __align__(16) float qs[Nn][16];   // 0.25-prescaled q, broadcast reads
    __shared__ float colsum[Nn];
    __shared__ float psum[8][17];
    int b = blockIdx.x >> 3, h = blockIdx.x & 7;
    int n = g_nobs[b];
    int tid = threadIdx.x;
    for (int idx = tid; idx < Nn*16; idx += 128){
        int jj = idx >> 4, c = idx & 15;
        bool v = (jj < n);
        ks[jj][c] = v ? g_k[(b*Nn + jj)*Dd + h*16 + c] : 0.f;
        qs[jj][c] = v ? 0.25f*g_q[(b*Nn + jj)*Dd + h*16 + c] : 0.f;
    }
    for (int idx = tid; idx < Nn; idx += 128) colsum[idx] = 0.f;
    __syncthreads();
    int w = tid >> 5, lane = tid & 31;
    float cs[8];
    #pragma unroll
    for (int r = 0; r < 8; r++) cs[r] = 0.f;
    for (int i0 = w*2; i0 < n; i0 += 8){
        // broadcast-load the two query rows (prescaled); 8 LDS.128 total
        const float4* q0v = (const float4*)&qs[i0][0];
        const float4* q1v = (const float4*)&qs[i0+1][0];
        float4 qa0 = q0v[0], qa1 = q0v[1], qa2 = q0v[2], qa3 = q0v[3];
        float4 qb0 = q1v[0], qb1 = q1v[1], qb2 = q1v[2], qb3 = q1v[3];
        float sc0[8], sc1[8];
        #pragma unroll
        for (int r = 0; r < 8; r++){
            int jj = lane + 32*r;
            const float4* kr = (const float4*)&ks[jj][0];
            float4 k0 = kr[0], k1 = kr[1], k2 = kr[2], k3 = kr[3];
            float s0, s1;
            s0  = qa0.x*k0.x + qa0.y*k0.y + qa0.z*k0.z + qa0.w*k0.w;
            s0 += qa1.x*k1.x + qa1.y*k1.y + qa1.z*k1.z + qa1.w*k1.w;
            s0 += qa2.x*k2.x + qa2.y*k2.y + qa2.z*k2.z + qa2.w*k2.w;
            s0 += qa3.x*k3.x + qa3.y*k3.y + qa3.z*k3.z + qa3.w*k3.w;
            s1  = qb0.x*k0.x + qb0.y*k0.y + qb0.z*k0.z + qb0.w*k0.w;
            s1 += qb1.x*k1.x + qb1.y*k1.y + qb1.z*k1.z + qb1.w*k1.w;
            s1 += qb2.x*k2.x + qb2.y*k2.y + qb2.z*k2.z + qb2.w*k2.w;
            s1 += qb3.x*k3.x + qb3.y*k3.y + qb3.z*k3.z + qb3.w*k3.w;
            bool valid = (jj < n);
            // exp without max-subtraction: scores bounded ~|4| << 88
            sc0[r] = __expf(valid ? s0 : -1e30f);
            sc1[r] = __expf(valid ? s1 : -1e30f);
        }
        float se0 = 0.f, se1 = 0.f;
        #pragma unroll
        for (int r = 0; r < 8; r++){ se0 += sc0[r]; se1 += sc1[r]; }
        #pragma unroll
        for (int off = 16; off; off >>= 1){
            se0 += __shfl_xor_sync(0xffffffffu, se0, off);
            se1 += __shfl_xor_sync(0xffffffffu, se1, off);
        }
        float inv0 = __fdividef(1.0f, se0);
        float inv1 = (i0 + 1 < n) ? __fdividef(1.0f, se1) : 0.f;
        #pragma unroll
        for (int r = 0; r < 8; r++) cs[r] += sc0[r]*inv0 + sc1[r]*inv1;
    }
    #pragma unroll
    for (int r = 0; r < 8; r++){
        int jj = lane + 32*r;
        atomicAdd(&colsum[jj], cs[r]);
    }
    __syncthreads();
    {
        int c = tid & 15, g = tid >> 4;   // 8 groups x 16 cols
        float acc = 0.f;
        for (int j = g; j < n; j += 8)
            acc += colsum[j] * g_v[(b*Nn + j)*Dd + h*16 + c];
        psum[g][c] = acc;
        __syncthreads();
        if (tid < 16){
            float s = 0.f;
            #pragma unroll
            for (int gg = 0; gg < 8; gg++) s += psum[gg][tid];
            g_attnsum[b*Dd + h*16 + tid] = s;
        }
    }
}

// ---- per-batch epilogue: Q_sub, w_sub, conf, alpha*fill ----
__global__ __launch_bounds__(128) void kfinal(
    const float* __restrict__ Wo,
    const float* __restrict__ C,
    const float* __restrict__ Wdec,
    float* __restrict__ outQ,
    float* __restrict__ outW,
    float* __restrict__ outC){
    __shared__ float sa[Dd], Qs[Dd], lg[Kk], wk[Kk], zc[Dd];
    __shared__ float s_alpha, s_conf;
    int b = blockIdx.x, d = threadIdx.x;
    int n = g_nobs[b];
    sa[d] = g_attnsum[b*Dd + d];
    __syncthreads();
    float q = 0.f;
    #pragma unroll 4
    for (int jj = 0; jj < Dd; jj++) q += sa[jj]*Wo[jj*Dd + d];
    q = (q + g_toksum[b*Dd + d])/(float)n;
    Qs[d] = q;
    __syncthreads();
    if (d < Kk){
        float lgv = 0.f;
        #pragma unroll 4
        for (int dd = 0; dd < Dd; dd++) lgv += Qs[dd]*C[d*Dd + dd];
        lg[d] = lgv * 2.0f;
    }
    __syncthreads();
    if (d == 0){
        float mx = -1e30f;
        for (int k = 0; k < Kk; k++) mx = fmaxf(mx, lg[k]);
        float s = 0.f;
        for (int k = 0; k < Kk; k++){ wk[k] = expf(lg[k]-mx); s += wk[k]; }
        float inv = 1.0f/s, wmax = 0.f;
        for (int k = 0; k < Kk; k++){ wk[k] *= inv; wmax = fmaxf(wmax, wk[k]); }
        float conf = wmax * ((float)n/(float)Nn);
        s_conf = conf;
        s_alpha = 0.1f + 0.9f*conf;
        if (outC) outC[b] = conf;
    }
    __syncthreads();
    float z = 0.f;
    #pragma unroll
    for (int k = 0; k < Kk; k++) z += wk[k]*C[k*Dd + d];
    zc[d] = z;
    __syncthreads();
    float f = 0.f;
    #pragma unroll 4
    for (int jj = 0; jj < Dd; jj++) f += zc[jj]*Wdec[jj*Dd + d];
    g_afill[b*Dd + d] = s_alpha * f;
    if (outQ) outQ[b*Dd + d] = q;
    if (outW && d < Kk) outW[b*Kk + d] = wk[d];
}

// ---- y_hat, 8 tokens per block ----
__global__ __launch_bounds__(256) void kyhat(
    const float* __restrict__ Wh,
    float* __restrict__ y){
    __shared__ __align__(16) float E[8][Dd];
    __shared__ __align__(16) float sWhT[PLl][132];
    int tid = threadIdx.x;
    int bn0 = blockIdx.x*8;
    int b = bn0 >> 8;
    for (int idx = tid; idx < 8*Dd; idx += 256){
        int t = idx >> 7, d = idx & 127;
        float m = g_maskf[bn0+t];
        E[t][d] = g_hmean[(bn0+t)*Dd + d] + (1.0f - m)*g_afill[b*Dd + d];
    }
    for (int idx = tid; idx < Dd*PLl; idx += 256){
        int d = idx / PLl, pl = idx - d*PLl;
        sWhT[pl][d] = Wh[idx];
    }
    __syncthreads();
    if (tid < 192){
        int t = tid / PLl, pl = tid - t*PLl;
        float acc = 0.f;
        const float4* ev = (const float4*)&E[t][0];
        const float4* wv = (const float4*)&sWhT[pl][0];
        #pragma unroll 8
        for (int d4 = 0; d4 < Dd/4; d4++){
            float4 e = ev[d4], w = wv[d4];
            acc += e.x*w.x + e.y*w.y + e.z*w.z + e.w*w.w;
        }
        y[(bn0+t)*PLl + pl] = acc;
    }
}

extern "C" void kernel_launch(void* const* d_in, const int* in_sizes, int n_in,
                              void* d_out, int out_size){
    const float* x    = (const float*)d_in[0];
    const void*  mask = d_in[1];
    const float* Wp   = (const float*)d_in[2];
    const float* bp   = (const float*)d_in[3];
    const float* W1   = (const float*)d_in[4];
    const float* W2   = (const float*)d_in[5];
    const float* ve   = (const float*)d_in[6];
    const float* Wq   = (const float*)d_in[7];
    const float* Wk   = (const float*)d_in[8];
    const float* Wv   = (const float*)d_in[9];
    const float* Wo   = (const float*)d_in[10];
    const float* C    = (const float*)d_in[11];
    const float* Wdec = (const float*)d_in[12];
    const float* Wh   = (const float*)d_in[13];

    float* out = (float*)d_out;
    const int SZ_Y = Bb*Nn*PLl;
    const int SZ_Q = Bb*Dd;
    const int SZ_W = Bb*Kk;
    float* oy = out;
    float* oq = (out_size >= SZ_Y + SZ_Q)              ? out + SZ_Y                : nullptr;
    float* ow = (out_size >= SZ_Y + SZ_Q + SZ_W)       ? out + SZ_Y + SZ_Q         : nullptr;
    float* oc = (out_size >= SZ_Y + SZ_Q + SZ_W + Bb)  ? out + SZ_Y + SZ_Q + SZ_W  : nullptr;

    kmaskfold<<<Bb+1, 256>>>((const unsigned char*)mask, Wp, bp, W1);
    kstage1<<<Bb*Nn/16, 256>>>(x, Wp, bp, W2);
    kqkv<<<Bb*Nn/16, 192>>>(Wq, Wk, Wv, ve);
    kattn<<<Bb*Hh, 128>>>();
    kfinal<<<Bb, Dd>>>(Wo, C, Wdec, oq, ow, oc);
    kyhat<<<Bb*Nn/8, 256>>>(Wh, oy);
}

// round 14
// speedup vs baseline: 1.3908x; 1.3908x over previous
#include <cuda_runtime.h>
#include <math.h>

// ---- problem constants ----
#define Bb 64
#define Nn 256
#define Tt 96
#define Pp 8
#define Ss 4
#define Dd 128
#define Hh 8
#define Kk 16
#define PLl 24
#define Ll 23

// ---- scratch ----
__device__ float g_maskf[Bb*Nn];
__device__ float g_wf[9*256];          // rows 0..7: (Wp@W1)[p][j]; row 8: bp@W1
__device__ __align__(16) float g_hmean[Bb*Nn*Dd];
__device__ int   g_obsidx[Bb*Nn];
__device__ int   g_nobs[Bb];
__device__ __align__(16) float g_q[Bb*Nn*Dd];
__device__ __align__(16) float g_k[Bb*Nn*Dd];
__device__ __align__(16) float g_v[Bb*Nn*Dd];
__device__ float g_attnsum[Bb*Dd];
__device__ float g_toksum[Bb*Dd];
__device__ float g_afill[Bb*Dd];

typedef unsigned long long u64;

#define FMA2(d,a,b,c) asm("fma.rn.f32x2 %0, %1, %2, %3;" : "=l"(d) : "l"(a), "l"(b), "l"(c))
#define MUL2(d,a,b)   asm("mul.rn.f32x2 %0, %1, %2;" : "=l"(d) : "l"(a), "l"(b))
#define ADD2(d,a,b)   asm("add.rn.f32x2 %0, %1, %2;" : "=l"(d) : "l"(a), "l"(b))
#define PACKF2(o,f)   asm("mov.b64 %0, {%1, %1};" : "=l"(o) : "r"(__float_as_uint(f)))
#define PACK2(o,a,b)  asm("mov.b64 %0, {%1, %2};" : "=l"(o) : "r"(__float_as_uint(a)), "r"(__float_as_uint(b)))
#define UNPACK2(a,b,i) asm("mov.b64 {%0, %1}, %2;" : "=r"(a), "=r"(b) : "l"(i))

__device__ __forceinline__ float f2lo(u64 v){ return __uint_as_float((unsigned)(v & 0xffffffffull)); }
__device__ __forceinline__ float f2hi(u64 v){ return __uint_as_float((unsigned)(v >> 32)); }

__device__ __forceinline__ float tanh_fast(float z){
    float t;
    asm("tanh.approx.f32 %0, %1;" : "=f"(t) : "f"(z));
    return t;
}

// ---- fused: blocks 0..63 = mask decode + compaction (per-block dtype sniff);
//             block 64 = fold Wp/bp into W1 ----
__global__ __launch_bounds__(256) void kmaskfold(const unsigned char* __restrict__ mp,
                                                 const float* __restrict__ Wp,
                                                 const float* __restrict__ bp,
                                                 const float* __restrict__ W1){
    int tid = threadIdx.x;
    if (blockIdx.x == Bb){
        __shared__ float sWp[Pp*Dd];
        __shared__ float sbp[Dd];
        for (int i = tid; i < Pp*Dd; i += 256) sWp[i] = Wp[i];
        if (tid < Dd) sbp[tid] = bp[tid];
        __syncthreads();
        int j = tid;
        float acc[9];
        #pragma unroll
        for (int p = 0; p < 9; p++) acc[p] = 0.f;
        for (int d = 0; d < Dd; d++){
            float w1 = W1[d*256 + j];
            #pragma unroll
            for (int p = 0; p < 8; p++) acc[p] += sWp[p*Dd + d]*w1;
            acc[8] += sbp[d]*w1;
        }
        #pragma unroll
        for (int p = 0; p < 9; p++) g_wf[p*256 + j] = acc[p];
        return;
    }
    __shared__ int sawF, sawB;
    __shared__ int wtot[8];
    __shared__ int wbase[9];
    if (tid == 0){ sawF = 0; sawB = 0; }
    __syncthreads();
    for (int i = tid; i < Bb*Nn; i += 256){
        unsigned char c = mp[i];
        if (c == 0x3f || c == 0x80) sawF = 1;
        else if (c != 0 && (i & 3) != 0) sawB = 1;
    }
    __syncthreads();
    int mode = sawF ? 0 : (sawB ? 2 : 1);
    int b = blockIdx.x;
    int i = b*Nn + tid;
    bool m;
    if (mode == 0)      m = ((const float*)mp)[i] != 0.0f;
    else if (mode == 1) m = ((const int*)mp)[i]   != 0;
    else                m = mp[i] != 0;
    g_maskf[i] = m ? 1.0f : 0.0f;
    unsigned bits = __ballot_sync(0xffffffffu, m);
    int w = tid >> 5, lane = tid & 31;
    int rank = __popc(bits & ((1u << lane) - 1u));
    if (lane == 0) wtot[w] = __popc(bits);
    __syncthreads();
    if (tid == 0){
        int s = 0;
        #pragma unroll
        for (int ww = 0; ww < 8; ww++){ wbase[ww] = s; s += wtot[ww]; }
        wbase[8] = s;
        g_nobs[b] = s;
    }
    __syncthreads();
    int total = wbase[8];
    int obs_before = wbase[w] + rank;
    int pos = m ? obs_before : total + (tid - obs_before);
    g_obsidx[b*Nn + pos] = tid;
    if (tid < Dd) g_toksum[b*Dd + tid] = 0.f;
}

// ---- stage 1: h_mean for 16 tokens per block, fully packed f32x2 ----
__global__ __launch_bounds__(256) void kstage1(
    const float* __restrict__ x,
    const float* __restrict__ Wp,
    const float* __restrict__ bp,
    const float* __restrict__ W2){
    __shared__ __align__(16) u64 sxp[8][96];
    __shared__ float sxs[16][Pp];
    __shared__ __align__(16) u64 sG2[256][10];
    __shared__ u64 sv2[8][Dd];
    int tid = threadIdx.x;
    int bn0 = blockIdx.x*16;

    for (int idx = tid; idx < 8*Tt; idx += 256){
        int tp = idx/Tt, c = idx - tp*Tt;
        float lo = x[(bn0+2*tp  )*Tt + c] * g_maskf[bn0+2*tp];
        float hi = x[(bn0+2*tp+1)*Tt + c] * g_maskf[bn0+2*tp+1];
        u64 pk; PACK2(pk, lo, hi);
        sxp[tp][c] = pk;
    }
    __syncthreads();
    if (tid < 128){
        int t = tid >> 3, p = tid & 7;
        int tp = t >> 1, half = t & 1;
        float s = 0.f;
        #pragma unroll
        for (int l = 0; l < Ll; l++){
            u64 v = sxp[tp][l*Ss + p];
            s += half ? f2hi(v) : f2lo(v);
        }
        sxs[t][p] = s;
    }

    {
        int j = tid;
        u64 wf2[8];
        #pragma unroll
        for (int p = 0; p < 8; p++) PACKF2(wf2[p], g_wf[p*256 + j]);
        u64 ub2; PACKF2(ub2, g_wf[8*256 + j]);
        u64 C1P, C2P, HALFP;
        PACKF2(C1P, 0.035677408136f);
        PACKF2(C2P, 0.797884560803f);
        PACKF2(HALFP, 0.5f);
        #pragma unroll 1
        for (int tp = 0; tp < 8; tp++){
            const ulonglong2* xv = (const ulonglong2*)&sxp[tp][0];
            ulonglong2 A = xv[0], Bv = xv[1];
            u64 Gp = 0ull;
            #pragma unroll
            for (int l = 0; l < Ll; l++){
                ulonglong2 Cv = xv[2*l+2], Dv = xv[2*l+3];
                u64 u = ub2;
                FMA2(u, A.x,  wf2[0], u); FMA2(u, A.y,  wf2[1], u);
                FMA2(u, Bv.x, wf2[2], u); FMA2(u, Bv.y, wf2[3], u);
                FMA2(u, Cv.x, wf2[4], u); FMA2(u, Cv.y, wf2[5], u);
                FMA2(u, Dv.x, wf2[6], u); FMA2(u, Dv.y, wf2[7], u);
                u64 x2p; MUL2(x2p, u, u);
                u64 t1;  FMA2(t1, C1P, x2p, C2P);
                u64 zp;  MUL2(zp, u, t1);
                unsigned zl, zh; UNPACK2(zl, zh, zp);
                float tl = tanh_fast(__uint_as_float(zl));
                float th = tanh_fast(__uint_as_float(zh));
                u64 tpk; PACK2(tpk, tl, th);
                u64 hxp; MUL2(hxp, u, HALFP);
                u64 res; FMA2(res, hxp, tpk, hxp);
                ADD2(Gp, Gp, res);
                A = Cv; Bv = Dv;
            }
            sG2[j][tp] = Gp;
        }
    }
    __syncthreads();

    {
        int d = tid & 127, h2 = tid >> 7;
        u64 acc[8];
        #pragma unroll
        for (int tp = 0; tp < 8; tp++) acc[tp] = 0ull;
        int j0 = h2*128;
        for (int j = j0; j < j0+128; j++){
            float w = W2[j*Dd + d];
            u64 w2; PACKF2(w2, w);
            const ulonglong2* gr = (const ulonglong2*)&sG2[j][0];
            ulonglong2 g01 = gr[0], g23 = gr[1], g45 = gr[2], g67 = gr[3];
            FMA2(acc[0], g01.x, w2, acc[0]); FMA2(acc[1], g01.y, w2, acc[1]);
            FMA2(acc[2], g23.x, w2, acc[2]); FMA2(acc[3], g23.y, w2, acc[3]);
            FMA2(acc[4], g45.x, w2, acc[4]); FMA2(acc[5], g45.y, w2, acc[5]);
            FMA2(acc[6], g67.x, w2, acc[6]); FMA2(acc[7], g67.y, w2, acc[7]);
        }
        if (h2){
            #pragma unroll
            for (int tp = 0; tp < 8; tp++) sv2[tp][d] = acc[tp];
        }
        __syncthreads();
        if (!h2){
            float bpd = 23.0f*bp[d];
            float wpc[8];
            #pragma unroll
            for (int p = 0; p < 8; p++) wpc[p] = Wp[p*Dd + d];
            #pragma unroll
            for (int tp = 0; tp < 8; tp++){
                u64 o = sv2[tp][d];
                float lo = f2lo(acc[tp]) + f2lo(o);
                float hi = f2hi(acc[tp]) + f2hi(o);
                int t0 = 2*tp;
                float hs0 = bpd, hs1 = bpd;
                #pragma unroll
                for (int p = 0; p < 8; p++){
                    hs0 += sxs[t0  ][p]*wpc[p];
                    hs1 += sxs[t0+1][p]*wpc[p];
                }
                g_hmean[(bn0+t0  )*Dd + d] = (hs0 + lo) * (1.0f/23.0f);
                g_hmean[(bn0+t0+1)*Dd + d] = (hs1 + hi) * (1.0f/23.0f);
            }
        }
    }
}

// ---- q/k/v: 16 tokens/block, 192 threads = 3 proj x 64 column-pairs ----
__global__ __launch_bounds__(192, 4) void kqkv(
    const float* __restrict__ Wq,
    const float* __restrict__ Wk,
    const float* __restrict__ Wv,
    const float* __restrict__ ve){
    __shared__ __align__(16) float tokT[Dd][20];
    int tid = threadIdx.x;
    int b = blockIdx.x >> 4;
    int i0 = (blockIdx.x & 15) * 16;
    int n = g_nobs[b];
    for (int idx = tid; idx < 16*Dd; idx += 192){
        int t = idx >> 7, d = idx & 127;
        int i = i0 + t;
        float val = 0.f;
        if (i < n){
            int src = g_obsidx[b*Nn + i];
            val = g_hmean[(b*Nn + src)*Dd + d] + ve[src*Dd + d];
        }
        tokT[d][t] = val;
    }
    __syncthreads();
    if (tid < Dd){
        const float4* r = (const float4*)&tokT[tid][0];
        float4 a = r[0], b4 = r[1], c4 = r[2], d4 = r[3];
        float s = a.x+a.y+a.z+a.w + b4.x+b4.y+b4.z+b4.w
                + c4.x+c4.y+c4.z+c4.w + d4.x+d4.y+d4.z+d4.w;
        atomicAdd(&g_toksum[b*Dd + tid], s);
    }
    int which = tid >> 6;
    int c0 = (tid & 63) * 2;
    const float* W = (which == 0) ? Wq : (which == 1 ? Wk : Wv);
    float* dst = (which == 0) ? g_q : (which == 1 ? g_k : g_v);
    u64 a0[8], a1[8];
    #pragma unroll
    for (int r = 0; r < 8; r++){ a0[r] = 0ull; a1[r] = 0ull; }
    for (int d = 0; d < Dd; d++){
        float2 w = *(const float2*)&W[d*Dd + c0];
        u64 w2a, w2b;
        PACKF2(w2a, w.x);
        PACKF2(w2b, w.y);
        const ulonglong2* row = (const ulonglong2*)&tokT[d][0];
        ulonglong2 p0 = row[0], p1 = row[1], p2 = row[2], p3 = row[3];
        FMA2(a0[0], p0.x, w2a, a0[0]); FMA2(a1[0], p0.x, w2b, a1[0]);
        FMA2(a0[1], p0.y, w2a, a0[1]); FMA2(a1[1], p0.y, w2b, a1[1]);
        FMA2(a0[2], p1.x, w2a, a0[2]); FMA2(a1[2], p1.x, w2b, a1[2]);
        FMA2(a0[3], p1.y, w2a, a0[3]); FMA2(a1[3], p1.y, w2b, a1[3]);
        FMA2(a0[4], p2.x, w2a, a0[4]); FMA2(a1[4], p2.x, w2b, a1[4]);
        FMA2(a0[5], p2.y, w2a, a0[5]); FMA2(a1[5], p2.y, w2b, a1[5]);
        FMA2(a0[6], p3.x, w2a, a0[6]); FMA2(a1[6], p3.x, w2b, a1[6]);
        FMA2(a0[7], p3.y, w2a, a0[7]); FMA2(a1[7], p3.y, w2b, a1[7]);
    }
    #pragma unroll
    for (int r = 0; r < 8; r++){
        float2 e0 = make_float2(f2lo(a0[r]), f2lo(a1[r]));
        float2 e1 = make_float2(f2hi(a0[r]), f2hi(a1[r]));
        *(float2*)&dst[(b*Nn + i0 + 2*r    )*Dd + c0] = e0;
        *(float2*)&dst[(b*Nn + i0 + 2*r + 1)*Dd + c0] = e1;
    }
}

// ---- attention per (b,h): 2 queries/iter, scalar accumulators, shuffle-broadcast q,
//      no-max softmax (scores provably small) ----
__global__ __launch_bounds__(256, 3) void kattn(){
    __shared__ __align__(16) float ks[Nn][20];   // K rows, conflict-free float4
    __shared__ float colsum[Nn];
    __shared__ float psum[16][17];
    int b = blockIdx.x >> 3, h = blockIdx.x & 7;
    int n = g_nobs[b];
    int tid = threadIdx.x;
    for (int idx = tid; idx < Nn*16; idx += 256){
        int jj = idx >> 4, c = idx & 15;
        ks[jj][c] = (jj < n) ? g_k[(b*Nn + jj)*Dd + h*16 + c] : 0.f;
    }
    for (int idx = tid; idx < Nn; idx += 256) colsum[idx] = 0.f;
    __syncthreads();
    int w = tid >> 5, lane = tid & 31;
    float cs[8];
    #pragma unroll
    for (int r = 0; r < 8; r++) cs[r] = 0.f;
    for (int i0 = w*2; i0 < n; i0 += 16){
        // lanes 0-15 carry 0.25*q[i0], lanes 16-31 carry 0.25*q[i0+1]
        float qv;
        if (lane < 16) qv = 0.25f*g_q[(b*Nn + i0)*Dd + h*16 + lane];
        else           qv = (i0 + 1 < n) ? 0.25f*g_q[(b*Nn + i0 + 1)*Dd + h*16 + (lane - 16)] : 0.f;
        float q0[16], q1[16];
        #pragma unroll
        for (int c = 0; c < 16; c++){
            q0[c] = __shfl_sync(0xffffffffu, qv, c);
            q1[c] = __shfl_sync(0xffffffffu, qv, 16 + c);
        }
        float sc0[8], sc1[8];
        #pragma unroll
        for (int r = 0; r < 8; r++){
            int jj = lane + 32*r;
            const float4* kr = (const float4*)&ks[jj][0];
            float4 k0 = kr[0], k1 = kr[1], k2 = kr[2], k3 = kr[3];
            float s0, s1;
            s0  = q0[0]*k0.x  + q0[1]*k0.y  + q0[2]*k0.z  + q0[3]*k0.w;
            s0 += q0[4]*k1.x  + q0[5]*k1.y  + q0[6]*k1.z  + q0[7]*k1.w;
            s0 += q0[8]*k2.x  + q0[9]*k2.y  + q0[10]*k2.z + q0[11]*k2.w;
            s0 += q0[12]*k3.x + q0[13]*k3.y + q0[14]*k3.z + q0[15]*k3.w;
            s1  = q1[0]*k0.x  + q1[1]*k0.y  + q1[2]*k0.z  + q1[3]*k0.w;
            s1 += q1[4]*k1.x  + q1[5]*k1.y  + q1[6]*k1.z  + q1[7]*k1.w;
            s1 += q1[8]*k2.x  + q1[9]*k2.y  + q1[10]*k2.z + q1[11]*k2.w;
            s1 += q1[12]*k3.x + q1[13]*k3.y + q1[14]*k3.z + q1[15]*k3.w;
            bool valid = (jj < n);
            // no-max softmax: |s| <~ 4 << 88, exp cannot overflow; invalid keys -> 0
            sc0[r] = valid ? __expf(s0) : 0.f;
            sc1[r] = valid ? __expf(s1) : 0.f;
        }
        float se0 = 0.f, se1 = 0.f;
        #pragma unroll
        for (int r = 0; r < 8; r++){ se0 += sc0[r]; se1 += sc1[r]; }
        #pragma unroll
        for (int off = 16; off; off >>= 1){
            se0 += __shfl_xor_sync(0xffffffffu, se0, off);
            se1 += __shfl_xor_sync(0xffffffffu, se1, off);
        }
        float inv0 = __fdividef(1.0f, se0);
        float inv1 = (i0 + 1 < n) ? __fdividef(1.0f, se1) : 0.f;
        #pragma unroll
        for (int r = 0; r < 8; r++) cs[r] += sc0[r]*inv0 + sc1[r]*inv1;
    }
    #pragma unroll
    for (int r = 0; r < 8; r++){
        int jj = lane + 32*r;
        atomicAdd(&colsum[jj], cs[r]);
    }
    __syncthreads();
    {
        int c = tid & 15, g = tid >> 4;
        float acc = 0.f;
        for (int j = g; j < n; j += 16)
            acc += colsum[j] * g_v[(b*Nn + j)*Dd + h*16 + c];
        psum[g][c] = acc;
        __syncthreads();
        if (tid < 16){
            float s = 0.f;
            #pragma unroll
            for (int gg = 0; gg < 16; gg++) s += psum[gg][tid];
            g_attnsum[b*Dd + h*16 + tid] = s;
        }
    }
}

// ---- per-batch epilogue: Q_sub, w_sub, conf, alpha*fill ----
__global__ __launch_bounds__(128) void kfinal(
    const float* __restrict__ Wo,
    const float* __restrict__ C,
    const float* __restrict__ Wdec,
    float* __restrict__ outQ,
    float* __restrict__ outW,
    float* __restrict__ outC){
    __shared__ float sa[Dd], Qs[Dd], lg[Kk], wk[Kk], zc[Dd];
    __shared__ float s_alpha, s_conf;
    int b = blockIdx.x, d = threadIdx.x;
    int n = g_nobs[b];
    sa[d] = g_attnsum[b*Dd + d];
    __syncthreads();
    float q = 0.f;
    #pragma unroll 4
    for (int jj = 0; jj < Dd; jj++) q += sa[jj]*Wo[jj*Dd + d];
    q = (q + g_toksum[b*Dd + d])/(float)n;
    Qs[d] = q;
    __syncthreads();
    if (d < Kk){
        float lgv = 0.f;
        #pragma unroll 4
        for (int dd = 0; dd < Dd; dd++) lgv += Qs[dd]*C[d*Dd + dd];
        lg[d] = lgv * 2.0f;
    }
    __syncthreads();
    if (d == 0){
        float mx = -1e30f;
        for (int k = 0; k < Kk; k++) mx = fmaxf(mx, lg[k]);
        float s = 0.f;
        for (int k = 0; k < Kk; k++){ wk[k] = expf(lg[k]-mx); s += wk[k]; }
        float inv = 1.0f/s, wmax = 0.f;
        for (int k = 0; k < Kk; k++){ wk[k] *= inv; wmax = fmaxf(wmax, wk[k]); }
        float conf = wmax * ((float)n/(float)Nn);
        s_conf = conf;
        s_alpha = 0.1f + 0.9f*conf;
        if (outC) outC[b] = conf;
    }
    __syncthreads();
    float z = 0.f;
    #pragma unroll
    for (int k = 0; k < Kk; k++) z += wk[k]*C[k*Dd + d];
    zc[d] = z;
    __syncthreads();
    float f = 0.f;
    #pragma unroll 4
    for (int jj = 0; jj < Dd; jj++) f += zc[jj]*Wdec[jj*Dd + d];
    g_afill[b*Dd + d] = s_alpha * f;
    if (outQ) outQ[b*Dd + d] = q;
    if (outW && d < Kk) outW[b*Kk + d] = wk[d];
}

// ---- y_hat, 8 tokens per block ----
__global__ __launch_bounds__(256) void kyhat(
    const float* __restrict__ Wh,
    float* __restrict__ y){
    __shared__ __align__(16) float E[8][Dd];
    __shared__ __align__(16) float sWhT[PLl][132];
    int tid = threadIdx.x;
    int bn0 = blockIdx.x*8;
    int b = bn0 >> 8;
    for (int idx = tid; idx < 8*Dd; idx += 256){
        int t = idx >> 7, d = idx & 127;
        float m = g_maskf[bn0+t];
        E[t][d] = g_hmean[(bn0+t)*Dd + d] + (1.0f - m)*g_afill[b*Dd + d];
    }
    for (int idx = tid; idx < Dd*PLl; idx += 256){
        int d = idx / PLl, pl = idx - d*PLl;
        sWhT[pl][d] = Wh[idx];
    }
    __syncthreads();
    if (tid < 192){
        int t = tid / PLl, pl = tid - t*PLl;
        float acc = 0.f;
        const float4* ev = (const float4*)&E[t][0];
        const float4* wv = (const float4*)&sWhT[pl][0];
        #pragma unroll 8
        for (int d4 = 0; d4 < Dd/4; d4++){
            float4 e = ev[d4], w = wv[d4];
            acc += e.x*w.x + e.y*w.y + e.z*w.z + e.w*w.w;
        }
        y[(bn0+t)*PLl + pl] = acc;
    }
}

extern "C" void kernel_launch(void* const* d_in, const int* in_sizes, int n_in,
                              void* d_out, int out_size){
    const float* x    = (const float*)d_in[0];
    const void*  mask = d_in[1];
    const float* Wp   = (const float*)d_in[2];
    const float* bp   = (const float*)d_in[3];
    const float* W1   = (const float*)d_in[4];
    const float* W2   = (const float*)d_in[5];
    const float* ve   = (const float*)d_in[6];
    const float* Wq   = (const float*)d_in[7];
    const float* Wk   = (const float*)d_in[8];
    const float* Wv   = (const float*)d_in[9];
    const float* Wo   = (const float*)d_in[10];
    const float* C    = (const float*)d_in[11];
    const float* Wdec = (const float*)d_in[12];
    const float* Wh   = (const float*)d_in[13];

    float* out = (float*)d_out;
    const int SZ_Y = Bb*Nn*PLl;
    const int SZ_Q = Bb*Dd;
    const int SZ_W = Bb*Kk;
    float* oy = out;
    float* oq = (out_size >= SZ_Y + SZ_Q)              ? out + SZ_Y                : nullptr;
    float* ow = (out_size >= SZ_Y + SZ_Q + SZ_W)       ? out + SZ_Y + SZ_Q         : nullptr;
    float* oc = (out_size >= SZ_Y + SZ_Q + SZ_W + Bb)  ? out + SZ_Y + SZ_Q + SZ_W  : nullptr;

    kmaskfold<<<Bb+1, 256>>>((const unsigned char*)mask, Wp, bp, W1);
    kstage1<<<Bb*Nn/16, 256>>>(x, Wp, bp, W2);
    kqkv<<<Bb*Nn/16, 192>>>(Wq, Wk, Wv, ve);
    kattn<<<Bb*Hh, 256>>>();
    kfinal<<<Bb, Dd>>>(Wo, C, Wdec, oq, ow, oc);
    kyhat<<<Bb*Nn/8, 256>>>(Wh, oy);
}